// round 3
// baseline (speedup 1.0000x reference)
#include <cuda_runtime.h>
#include <cuda_bf16.h>
#include <float.h>

// Problem constants
#define KCODES   4096
#define DIMS     256
#define NROWS    32768            // 32 * 32 * 32
#define ZELEMS   8388608          // 32*256*32*32
#define LOSS_OFF 8388608
#define IDX_OFF  8388609

// Main GEMM tiling
#define ROWS_PER_CTA 64
#define NCTA        (NROWS / ROWS_PER_CTA)   // 512
#define THREADS     256
#define CODES_PER_CHUNK 128                  // 16 tx * 8
#define NCHUNKS     (KCODES / CODES_PER_CHUNK) // 32
#define DCHUNK      32                       // depth chunk
#define NDCHUNKS    (DIMS / DCHUNK)          // 8

#define ZS_STRIDE 68      // 64 rows + pad, float4-aligned
#define CB_STRIDE 132     // 128 codes + pad, float4-aligned

// smem partition (floats)
#define ZS_FLOATS   (DIMS * ZS_STRIDE)        // 17408
#define CBS_FLOATS  (DCHUNK * CB_STRIDE)      // 4224
#define ESQ_FLOATS  (KCODES)                  // 4096
#define ZSQ_FLOATS  (ROWS_PER_CTA)            // 64
#define SMEM_FLOATS (ZS_FLOATS + CBS_FLOATS + ESQ_FLOATS + ZSQ_FLOATS)
#define SMEM_BYTES  (SMEM_FLOATS * 4)         // 103168

__device__ float  g_esq[KCODES];
__device__ int    g_idx[NROWS];
__device__ double g_partials[NCTA];

// ---------------------------------------------------------------------------
// Kernel 1: e_sq[k] = sum_d codebook[k][d]^2   (one warp per code)
// ---------------------------------------------------------------------------
__global__ void vq_esq_kernel(const float* __restrict__ cb) {
    int warp = (blockIdx.x * blockDim.x + threadIdx.x) >> 5;
    int lane = threadIdx.x & 31;
    if (warp >= KCODES) return;
    const float4* row = reinterpret_cast<const float4*>(cb) + (size_t)warp * 64;
    float4 v0 = row[lane];
    float4 v1 = row[lane + 32];
    float s = 0.0f;
    s = fmaf(v0.x, v0.x, s); s = fmaf(v0.y, v0.y, s);
    s = fmaf(v0.z, v0.z, s); s = fmaf(v0.w, v0.w, s);
    s = fmaf(v1.x, v1.x, s); s = fmaf(v1.y, v1.y, s);
    s = fmaf(v1.z, v1.z, s); s = fmaf(v1.w, v1.w, s);
    #pragma unroll
    for (int o = 16; o > 0; o >>= 1) s += __shfl_down_sync(0xffffffffu, s, o);
    if (lane == 0) g_esq[warp] = s;
}

// ---------------------------------------------------------------------------
// Kernel 2: distance GEMM + argmin, inner loop on packed fma.rn.f32x2 (FFMA2).
// Each f32x2 lane is an independent sequential fp32 FMA chain over d (same
// order as round 2) -> bit-identical dots -> bit-identical argmin.
// CTA: 64 rows; thread (ty,tx)=(tid/16,tid%16) owns a 4x8 tile.
// ---------------------------------------------------------------------------
__global__ void __launch_bounds__(THREADS, 2)
vq_main_kernel(const float* __restrict__ z, const float* __restrict__ cb) {
    extern __shared__ float smem[];
    float* zs    = smem;                       // [256][68] d-major z tile
    float* cbs   = zs + ZS_FLOATS;             // [32][132] d-major cb chunk
    float* esq_s = cbs + CBS_FLOATS;           // [4096]
    float* zsq   = esq_s + ESQ_FLOATS;         // [64]

    const int t   = threadIdx.x;
    const int n0  = blockIdx.x * ROWS_PER_CTA;
    const int b   = n0 >> 10;
    const int hw0 = n0 & 1023;
    const float* zb = z + ((size_t)b * 256) * 1024 + hw0;

    // ---- load z tile (d-major) ----
    {
        const int r  = t & 63;
        const int dq = t >> 6;            // 0..3
        #pragma unroll 4
        for (int p = 0; p < 64; ++p) {
            int d = p * 4 + dq;
            zs[d * ZS_STRIDE + r] = zb[(size_t)d * 1024 + r];
        }
    }
    // ---- load e_sq into smem ----
    for (int i = t; i < KCODES; i += THREADS) esq_s[i] = g_esq[i];
    __syncthreads();

    // ---- z_sq per row (same order as round 2: bit-stable vs reference) ----
    {
        const int warp = t >> 5;
        const int lane = t & 31;
        for (int rr = warp * 8; rr < warp * 8 + 8; ++rr) {
            float s = 0.0f;
            #pragma unroll
            for (int j = 0; j < 8; ++j) {
                float v = zs[(lane + 32 * j) * ZS_STRIDE + rr];
                s = fmaf(v, v, s);
            }
            #pragma unroll
            for (int o = 16; o > 0; o >>= 1) s += __shfl_down_sync(0xffffffffu, s, o);
            if (lane == 0) zsq[rr] = s;
        }
    }
    __syncthreads();

    const int ty = t >> 4;
    const int tx = t & 15;
    const int r0 = ty * 4;

    float sqv[4];
    #pragma unroll
    for (int i = 0; i < 4; ++i) sqv[i] = zsq[r0 + i];

    float bv[4]; int bi[4];
    #pragma unroll
    for (int i = 0; i < 4; ++i) { bv[i] = FLT_MAX; bi[i] = 0; }

    const float4* cb4 = reinterpret_cast<const float4*>(cb);

    for (int kc = 0; kc < NCHUNKS; ++kc) {
        const int k0 = kc * CODES_PER_CHUNK;

        // packed accumulators: acc2[i][jp] = (dot(i, 2jp), dot(i, 2jp+1))
        unsigned long long acc2[4][4];
        #pragma unroll
        for (int i = 0; i < 4; ++i)
            #pragma unroll
            for (int jp = 0; jp < 4; ++jp) acc2[i][jp] = 0ull;

        // prefetch depth-chunk 0 into registers
        float4 pf[4];
        #pragma unroll
        for (int it = 0; it < 4; ++it) {
            int idx = it * 256 + t;
            int c = idx >> 3, q = idx & 7;
            pf[it] = cb4[(size_t)(k0 + c) * 64 + q];
        }

        for (int dc = 0; dc < NDCHUNKS; ++dc) {
            __syncthreads();   // previous chunk's compute done
            // stage registers -> smem (transpose to d-major)
            #pragma unroll
            for (int it = 0; it < 4; ++it) {
                int idx = it * 256 + t;
                int c = idx >> 3, q = idx & 7;
                float* p = &cbs[(q * 4) * CB_STRIDE + c];
                p[0 * CB_STRIDE] = pf[it].x;
                p[1 * CB_STRIDE] = pf[it].y;
                p[2 * CB_STRIDE] = pf[it].z;
                p[3 * CB_STRIDE] = pf[it].w;
            }
            __syncthreads();
            // prefetch next depth chunk
            if (dc + 1 < NDCHUNKS) {
                #pragma unroll
                for (int it = 0; it < 4; ++it) {
                    int idx = it * 256 + t;
                    int c = idx >> 3, q = idx & 7;
                    pf[it] = cb4[(size_t)(k0 + c) * 64 + (dc + 1) * 8 + q];
                }
            }
            const int dbase = dc * DCHUNK;
            #pragma unroll 8
            for (int dd = 0; dd < DCHUNK; ++dd) {
                const float4 a4 = *reinterpret_cast<const float4*>(
                    &zs[(dbase + dd) * ZS_STRIDE + r0]);
                // b pairs: adjacent floats in d-major cb tile ARE the packed
                // f32x2 operands -> load directly as 64-bit values (no movs)
                const ulonglong2 bq0 = *reinterpret_cast<const ulonglong2*>(
                    &cbs[dd * CB_STRIDE + tx * 8]);
                const ulonglong2 bq1 = *reinterpret_cast<const ulonglong2*>(
                    &cbs[dd * CB_STRIDE + tx * 8 + 4]);
                const unsigned long long bp[4] = {bq0.x, bq0.y, bq1.x, bq1.y};
                const float a[4] = {a4.x, a4.y, a4.z, a4.w};
                #pragma unroll
                for (int i = 0; i < 4; ++i) {
                    unsigned long long ap;
                    asm("mov.b64 %0, {%1, %1};" : "=l"(ap) : "f"(a[i]));
                    #pragma unroll
                    for (int jp = 0; jp < 4; ++jp) {
                        asm("fma.rn.f32x2 %0, %1, %2, %0;"
                            : "+l"(acc2[i][jp]) : "l"(ap), "l"(bp[jp]));
                    }
                }
            }
        }

        // unpack + distances + running argmin.
        // Replicate reference rounding exactly: fl(fl(z_sq - 2*dot) + e_sq).
        #pragma unroll
        for (int jp = 0; jp < 4; ++jp) {
            #pragma unroll
            for (int i = 0; i < 4; ++i) {
                float dlo, dhi;
                asm("mov.b64 {%0, %1}, %2;" : "=f"(dlo), "=f"(dhi) : "l"(acc2[i][jp]));
                int klo = k0 + tx * 8 + 2 * jp;
                float elo = esq_s[klo];
                float ehi = esq_s[klo + 1];
                float distlo = __fadd_rn(__fsub_rn(sqv[i], __fmul_rn(2.0f, dlo)), elo);
                float disthi = __fadd_rn(__fsub_rn(sqv[i], __fmul_rn(2.0f, dhi)), ehi);
                if (distlo < bv[i]) { bv[i] = distlo; bi[i] = klo; }
                if (disthi < bv[i]) { bv[i] = disthi; bi[i] = klo + 1; }
            }
        }
    }

    // reduce across the 16 tx threads (one half-warp per row group)
    #pragma unroll
    for (int i = 0; i < 4; ++i) {
        float v = bv[i]; int x = bi[i];
        #pragma unroll
        for (int off = 8; off > 0; off >>= 1) {
            float ov = __shfl_down_sync(0xffffffffu, v, off, 16);
            int   ox = __shfl_down_sync(0xffffffffu, x, off, 16);
            if (ov < v || (ov == v && ox < x)) { v = ov; x = ox; }
        }
        if (tx == 0) g_idx[n0 + r0 + i] = x;
    }
}

// ---------------------------------------------------------------------------
// Kernel 3: gather codebook rows, write z_q_st (+ indices-as-float), and
// per-block double loss partials.
// ---------------------------------------------------------------------------
__global__ void __launch_bounds__(THREADS)
vq_epilogue_kernel(const float* __restrict__ z, const float* __restrict__ cb,
                   float* __restrict__ out, int out_size) {
    __shared__ int idx_s[ROWS_PER_CTA];
    __shared__ double red[THREADS];

    const int t  = threadIdx.x;
    const int n0 = blockIdx.x * ROWS_PER_CTA;

    if (t < ROWS_PER_CTA) {
        int ii = g_idx[n0 + t];
        idx_s[t] = ii;
        int oi = IDX_OFF + n0 + t;
        if (oi < out_size) out[oi] = (float)ii;  // indices cast to f32 (exact)
    }
    __syncthreads();

    const int b   = n0 >> 10;
    const int hw0 = n0 & 1023;
    const float* zb = z + ((size_t)b * 256) * 1024 + hw0;
    float*       ob = out + ((size_t)b * 256) * 1024 + hw0;

    const int r  = t & 63;
    const int dq = t >> 6;                 // thread owns d in [dq*64, dq*64+64)
    const float* cbrow = cb + (size_t)idx_s[r] * DIMS;

    double accd = 0.0;
    #pragma unroll 4
    for (int p4 = 0; p4 < 16; ++p4) {
        const float4 q4 = *reinterpret_cast<const float4*>(cbrow + dq * 64 + p4 * 4);
        const float qv[4] = {q4.x, q4.y, q4.z, q4.w};
        #pragma unroll
        for (int j = 0; j < 4; ++j) {
            int d = dq * 64 + p4 * 4 + j;
            float zv = zb[(size_t)d * 1024 + r];
            float diff = __fsub_rn(qv[j], zv);
            ob[(size_t)d * 1024 + r] = __fadd_rn(zv, diff);  // straight-through
            accd = fma((double)diff, (double)diff, accd);
        }
    }

    red[t] = accd;
    __syncthreads();
    for (int s = THREADS / 2; s > 0; s >>= 1) {
        if (t < s) red[t] += red[t + s];
        __syncthreads();
    }
    if (t == 0) g_partials[blockIdx.x] = red[0];
}

// ---------------------------------------------------------------------------
// Kernel 4: final loss reduction (deterministic fixed-order tree).
// vq_loss = mean + 0.25*mean  (codebook_loss == commitment_loss numerically)
// ---------------------------------------------------------------------------
__global__ void vq_finalize_kernel(float* __restrict__ out, int out_size) {
    __shared__ double red[256];
    const int t = threadIdx.x;
    red[t] = g_partials[t] + g_partials[t + 256];
    __syncthreads();
    for (int s = 128; s > 0; s >>= 1) {
        if (t < s) red[t] += red[t + s];
        __syncthreads();
    }
    if (t == 0 && LOSS_OFF < out_size) {
        double mean = red[0] / (double)ZELEMS;
        float m = (float)mean;
        out[LOSS_OFF] = __fadd_rn(m, __fmul_rn(0.25f, m));
    }
}

// ---------------------------------------------------------------------------
extern "C" void kernel_launch(void* const* d_in, const int* in_sizes, int n_in,
                              void* d_out, int out_size) {
    const float* z  = (const float*)d_in[0];
    const float* cb = (const float*)d_in[1];
    // defensive: detect swapped input order by element count
    if (n_in >= 2 && in_sizes[0] == KCODES * DIMS && in_sizes[1] == ZELEMS) {
        const float* tmp = z; z = cb; cb = tmp;
    }
    float* out = (float*)d_out;

    cudaFuncSetAttribute(vq_main_kernel,
                         cudaFuncAttributeMaxDynamicSharedMemorySize, SMEM_BYTES);

    vq_esq_kernel<<<KCODES / 8, 256>>>(cb);
    vq_main_kernel<<<NCTA, THREADS, SMEM_BYTES>>>(z, cb);
    vq_epilogue_kernel<<<NCTA, THREADS>>>(z, cb, out, out_size);
    vq_finalize_kernel<<<1, 256>>>(out, out_size);
}

// round 5
// speedup vs baseline: 5.7884x; 5.7884x over previous
#include <cuda_runtime.h>
#include <cuda_bf16.h>
#include <float.h>
#include <stdint.h>

// ============================ problem constants ============================
#define KCODES   4096
#define DIMS     256
#define NROWS    32768
#define ZELEMS   8388608
#define LOSS_OFF 8388608
#define IDX_OFF  8388609

// ============================ main GEMM config =============================
#define MT          128                  // z rows per CTA
#define NMMACTA     (NROWS / MT)         // 256 CTAs
#define NCODE       128                  // codes per chunk
#define NCHUNKS     (KCODES / NCODE)     // 32
#define DELTA       7.5e-4f              // provable-argmin margin

#define ROW_BYTES   528                  // 256 bf16 (512B) + 16B pad: LDSM conflict-free
#define TILE_BYTES  (128 * ROW_BYTES)    // 67584 per A / B buffer
#define SM_A        0
#define SM_B0       TILE_BYTES
#define SM_B1       (2 * TILE_BYTES)
#define SM_MRG      (3 * TILE_BYTES)     // merge: 2*512 floats + 512 ints = 6144
#define SM_TOTAL    (3 * TILE_BYTES + 6144)   // 208896 bytes

// epilogue kernel tiling (validated in round 2)
#define EP_ROWS  64
#define EP_NCTA  (NROWS / EP_ROWS)       // 512
#define EP_THREADS 256

// ============================ device globals ===============================
__device__ float  g_esq[KCODES];
__device__ int    g_idx[NROWS];
__device__ double g_partials[EP_NCTA];
__device__ __align__(16) __nv_bfloat16 g_zh[NROWS * DIMS];       // z, row-major (n,d)
__device__ __align__(16) __nv_bfloat16 g_cbh[KCODES * DIMS];     // codebook bf16
__device__ int g_ucount;
__device__ int g_ulist[NROWS];

// ============================ PTX helpers ==================================
__device__ __forceinline__ uint32_t smem_u32(const void* p) {
    uint32_t a;
    asm("{ .reg .u64 t; cvta.to.shared.u64 t, %1; cvt.u32.u64 %0, t; }"
        : "=r"(a) : "l"(p));
    return a;
}

#define CP_ASYNC16(dst, src) \
    asm volatile("cp.async.cg.shared.global [%0], [%1], 16;" \
                 :: "r"(dst), "l"(src) : "memory")
#define CP_COMMIT() asm volatile("cp.async.commit_group;" ::: "memory")
#define CP_WAIT(n)  asm volatile("cp.async.wait_group %0;" :: "n"(n) : "memory")

#define LDSM_X4(r0, r1, r2, r3, addr) \
    asm volatile("ldmatrix.sync.aligned.m8n8.x4.shared.b16 {%0,%1,%2,%3}, [%4];" \
                 : "=r"(r0), "=r"(r1), "=r"(r2), "=r"(r3) : "r"(addr))

#define MMA_BF16(acc, a, b0, b1) \
    asm volatile("mma.sync.aligned.m16n8k16.row.col.f32.bf16.bf16.f32 " \
        "{%0,%1,%2,%3}, {%4,%5,%6,%7}, {%8,%9}, {%0,%1,%2,%3};" \
        : "+f"((acc)[0]), "+f"((acc)[1]), "+f"((acc)[2]), "+f"((acc)[3]) \
        : "r"((a)[0]), "r"((a)[1]), "r"((a)[2]), "r"((a)[3]), \
          "r"(b0), "r"(b1))

// ============================ kernel 0a: z transpose -> bf16 ================
// z (b, d, hw) fp32 -> g_zh[n = b*1024+hw][d] bf16
__global__ void vq_zprep(const float* __restrict__ z) {
    __shared__ float tile[32][33];
    const int bidx = blockIdx.x;              // 32 b * 8 dt * 32 ht = 8192
    const int b  = bidx >> 8;
    const int dt = (bidx >> 5) & 7;
    const int ht = bidx & 31;
    const int tx = threadIdx.x & 31;
    const int ty = threadIdx.x >> 5;          // 0..7
    const float* zp = z + ((size_t)b * 256 + dt * 32) * 1024 + ht * 32;
    #pragma unroll
    for (int i = 0; i < 4; ++i)
        tile[ty + 8 * i][tx] = zp[(size_t)(ty + 8 * i) * 1024 + tx];
    __syncthreads();
    __nv_bfloat16* dst = g_zh + ((size_t)b * 1024 + ht * 32) * 256 + dt * 32;
    #pragma unroll
    for (int i = 0; i < 4; ++i) {
        int r = ty + 8 * i;
        dst[(size_t)r * 256 + tx] = __float2bfloat16(tile[tx][r]);
    }
}

// ============================ kernel 0b: cb -> bf16, reset counter =========
__global__ void vq_cbprep(const float* __restrict__ cb) {
    int i = blockIdx.x * 256 + threadIdx.x;
    if (i == 0) g_ucount = 0;
    if (i < KCODES * DIMS) g_cbh[i] = __float2bfloat16(cb[i]);
}

// ============================ kernel 0c: e_sq ==============================
__global__ void vq_esq_kernel(const float* __restrict__ cb) {
    int warp = (blockIdx.x * blockDim.x + threadIdx.x) >> 5;
    int lane = threadIdx.x & 31;
    if (warp >= KCODES) return;
    const float4* row = reinterpret_cast<const float4*>(cb) + (size_t)warp * 64;
    float4 v0 = row[lane];
    float4 v1 = row[lane + 32];
    float s = 0.0f;
    s = fmaf(v0.x, v0.x, s); s = fmaf(v0.y, v0.y, s);
    s = fmaf(v0.z, v0.z, s); s = fmaf(v0.w, v0.w, s);
    s = fmaf(v1.x, v1.x, s); s = fmaf(v1.y, v1.y, s);
    s = fmaf(v1.z, v1.z, s); s = fmaf(v1.w, v1.w, s);
    #pragma unroll
    for (int o = 16; o > 0; o >>= 1) s += __shfl_down_sync(0xffffffffu, s, o);
    if (lane == 0) g_esq[warp] = s;
}

// ============================ kernel 1: HMMA GEMM + margin argmin ==========
// CTA: 128 z rows x all 4096 codes, K=256 bf16, chunks of 128 codes.
// 8 warps: mw = w&1 (2 groups of 64 rows), nw = w>>1 (4 groups of 32 codes).
// Warp tile 64x32 via m16n8k16: 4 m-frags x 4 n-frags, 64 fp32 accs/thread.
// Dists are shifted by -z_sq (constant per row -> cancels in argmin/gap).
__global__ void __launch_bounds__(256, 1)
vq_mma_kernel() {
    extern __shared__ char sm[];
    const uint32_t smb = smem_u32(sm);
    const int tid  = threadIdx.x;
    const int lane = tid & 31;
    const int w    = tid >> 5;
    const int mw   = w & 1;
    const int nw   = w >> 1;
    const int n0   = blockIdx.x * MT;

    // ---- stage A (z rows) + B chunk 0 via cp.async ----
    {
        const char* srcA = (const char*)g_zh + (size_t)n0 * 512;
        const char* srcB = (const char*)g_cbh;
        #pragma unroll
        for (int i = 0; i < 16; ++i) {
            int seg = tid + i * 256;            // 0..4095
            int rc = seg >> 5, s = seg & 31;
            CP_ASYNC16(smb + SM_A + rc * ROW_BYTES + s * 16,
                       srcA + (size_t)rc * 512 + s * 16);
        }
        #pragma unroll
        for (int i = 0; i < 16; ++i) {
            int seg = tid + i * 256;
            int rc = seg >> 5, s = seg & 31;
            CP_ASYNC16(smb + SM_B0 + rc * ROW_BYTES + s * 16,
                       srcB + (size_t)rc * 512 + s * 16);
        }
        CP_COMMIT();
    }

    // per-thread ldmatrix base offsets (t0-7: rows0-7 ch0; t8-15: rows8-15 ch0;
    // t16-23: rows0-7 ch1; t24-31: rows8-15 ch1)
    const uint32_t lr = (uint32_t)((lane & 7) + ((lane >> 3) & 1) * 8);
    const uint32_t ch = (uint32_t)((lane >> 4) & 1);
    const uint32_t a_base = smb + SM_A + (mw * 64 + lr) * ROW_BYTES + ch * 16;
    const uint32_t b_off  = (nw * 32 + lr) * ROW_BYTES + ch * 16;

    float v1[8], v2[8]; int i1[8];
    #pragma unroll
    for (int r = 0; r < 8; ++r) { v1[r] = FLT_MAX; v2[r] = FLT_MAX; i1[r] = 0; }

    for (int c = 0; c < NCHUNKS; ++c) {
        if (c < NCHUNKS - 1) {
            const char* srcB = (const char*)g_cbh + (size_t)(c + 1) * NCODE * 512;
            uint32_t dstB = smb + (((c + 1) & 1) ? SM_B1 : SM_B0);
            #pragma unroll
            for (int i = 0; i < 16; ++i) {
                int seg = tid + i * 256;
                int rc = seg >> 5, s = seg & 31;
                CP_ASYNC16(dstB + rc * ROW_BYTES + s * 16,
                           srcB + (size_t)rc * 512 + s * 16);
            }
            CP_COMMIT();
            CP_WAIT(1);
        } else {
            CP_WAIT(0);
        }
        __syncthreads();

        const uint32_t bbuf = smb + ((c & 1) ? SM_B1 : SM_B0);

        float acc[4][4][4];
        #pragma unroll
        for (int mf = 0; mf < 4; ++mf)
            #pragma unroll
            for (int nf = 0; nf < 4; ++nf)
                #pragma unroll
                for (int i = 0; i < 4; ++i) acc[mf][nf][i] = 0.0f;

        #pragma unroll 4
        for (int ks = 0; ks < 16; ++ks) {
            uint32_t a[4][4];
            #pragma unroll
            for (int mf = 0; mf < 4; ++mf)
                LDSM_X4(a[mf][0], a[mf][1], a[mf][2], a[mf][3],
                        a_base + mf * (16 * ROW_BYTES) + ks * 32);
            uint32_t bf[2][4];
            #pragma unroll
            for (int p = 0; p < 2; ++p)
                LDSM_X4(bf[p][0], bf[p][1], bf[p][2], bf[p][3],
                        bbuf + b_off + p * (16 * ROW_BYTES) + ks * 32);
            // ldsm x4 on 16(codes)x16(k): r0=(c0-7,k0-7) r1=(c8-15,k0-7)
            //                             r2=(c0-7,k8-15) r3=(c8-15,k8-15)
            #pragma unroll
            for (int mf = 0; mf < 4; ++mf) {
                #pragma unroll
                for (int p = 0; p < 2; ++p) {
                    MMA_BF16(acc[mf][p * 2 + 0], a[mf], bf[p][0], bf[p][2]);
                    MMA_BF16(acc[mf][p * 2 + 1], a[mf], bf[p][1], bf[p][3]);
                }
            }
        }

        // ---- shifted dists + running (best, second-best) ----
        const int kbase = c * NCODE + nw * 32;
        #pragma unroll
        for (int nf = 0; nf < 4; ++nf) {
            int kc = kbase + nf * 8 + (lane & 3) * 2;
            float2 e2 = *reinterpret_cast<const float2*>(&g_esq[kc]);
            #pragma unroll
            for (int mf = 0; mf < 4; ++mf) {
                #pragma unroll
                for (int i = 0; i < 4; ++i) {
                    int ri = mf * 2 + (i >> 1);
                    float e = (i & 1) ? e2.y : e2.x;
                    float d = fmaf(-2.0f, acc[mf][nf][i], e);
                    if (d < v2[ri]) {
                        if (d < v1[ri]) {
                            v2[ri] = v1[ri]; v1[ri] = d; i1[ri] = kc + (i & 1);
                        } else v2[ri] = d;
                    }
                }
            }
        }
        __syncthreads();
    }

    // ---- merge across the 4 lanes of each quad (same rows, different cols) --
    #pragma unroll
    for (int r = 0; r < 8; ++r) {
        #pragma unroll
        for (int off = 1; off < 4; off <<= 1) {
            float ov1 = __shfl_xor_sync(0xffffffffu, v1[r], off);
            float ov2 = __shfl_xor_sync(0xffffffffu, v2[r], off);
            int   oi  = __shfl_xor_sync(0xffffffffu, i1[r], off);
            float lo = fminf(v1[r], ov1);
            float hi = fmaxf(v1[r], ov1);
            float s2 = fminf(fminf(v2[r], ov2), hi);
            if (ov1 < v1[r] || (ov1 == v1[r] && oi < i1[r])) i1[r] = oi;
            v1[r] = lo; v2[r] = s2;
        }
    }

    // ---- cross-warp merge via smem, margin test ----
    float* mv1 = reinterpret_cast<float*>(sm + SM_MRG);
    float* mv2 = mv1 + 512;
    int*   mi  = reinterpret_cast<int*>(mv2 + 512);
    if ((lane & 3) == 0) {
        int q = lane >> 2;
        #pragma unroll
        for (int mf = 0; mf < 4; ++mf)
            #pragma unroll
            for (int dlt = 0; dlt < 2; ++dlt) {
                int row = mw * 64 + mf * 16 + dlt * 8 + q;
                int r = mf * 2 + dlt;
                mv1[nw * 128 + row] = v1[r];
                mv2[nw * 128 + row] = v2[r];
                mi [nw * 128 + row] = i1[r];
            }
    }
    __syncthreads();
    if (tid < 128) {
        float bv1 = mv1[tid], bv2 = mv2[tid];
        int   bi  = mi[tid];
        #pragma unroll
        for (int g = 1; g < 4; ++g) {
            float ov1 = mv1[g * 128 + tid], ov2 = mv2[g * 128 + tid];
            int   oi  = mi[g * 128 + tid];
            float lo = fminf(bv1, ov1);
            float hi = fmaxf(bv1, ov1);
            bv2 = fminf(fminf(bv2, ov2), hi);
            if (ov1 < bv1 || (ov1 == bv1 && oi < bi)) bi = oi;
            bv1 = lo;
        }
        int n = n0 + tid;
        if (__fsub_rn(bv2, bv1) > DELTA) {
            g_idx[n] = bi;                      // provably the reference argmin
        } else {
            int p = atomicAdd(&g_ucount, 1);    // near-tie -> exact rescore
            g_ulist[p] = n;
        }
    }
}

// ============================ kernel 2: exact fallback =====================
// Bit-replicates round-2 arithmetic (sequential-d fmaf dot, same z_sq tree,
// fl(fl(zsq-2dot)+esq), packed-min first-index tie-break).
__global__ void __launch_bounds__(512)
vq_fallback_kernel(const float* __restrict__ z, const float* __restrict__ cb) {
    __shared__ float zrow[8][256];
    __shared__ float zsqs[8];
    __shared__ int   rown[8];
    __shared__ unsigned long long red[512];

    const int t = threadIdx.x;
    const int cnt = g_ucount;

    for (int base = blockIdx.x * 8; base < cnt; base += gridDim.x * 8) {
        const int nr = min(8, cnt - base);
        if (t < nr) rown[t] = g_ulist[base + t];
        __syncthreads();
        for (int e = t; e < nr * 256; e += 512) {
            int j = e >> 8, d = e & 255;
            int n = rown[j], bb = n >> 10, hw = n & 1023;
            zrow[j][d] = z[((size_t)bb * 256 + d) * 1024 + hw];
        }
        __syncthreads();
        {
            int wj = t >> 5, lane = t & 31;
            if (wj < nr) {
                float s = 0.0f;
                #pragma unroll
                for (int j = 0; j < 8; ++j) {
                    float v = zrow[wj][lane + 32 * j];
                    s = fmaf(v, v, s);
                }
                #pragma unroll
                for (int o = 16; o > 0; o >>= 1) s += __shfl_down_sync(0xffffffffu, s, o);
                if (lane == 0) zsqs[wj] = s;
            }
        }
        __syncthreads();

        unsigned long long best[8];
        #pragma unroll
        for (int j = 0; j < 8; ++j) best[j] = ~0ull;

        for (int k = t; k < KCODES; k += 512) {
            const float4* er = reinterpret_cast<const float4*>(cb + (size_t)k * DIMS);
            float dot[8];
            #pragma unroll
            for (int j = 0; j < 8; ++j) dot[j] = 0.0f;
            for (int q = 0; q < 64; ++q) {
                float4 e4 = er[q];
                float ev[4] = {e4.x, e4.y, e4.z, e4.w};
                #pragma unroll
                for (int x = 0; x < 4; ++x) {
                    int d = q * 4 + x;
                    #pragma unroll
                    for (int j = 0; j < 8; ++j)
                        dot[j] = fmaf(zrow[j][d], ev[x], dot[j]);
                }
            }
            float es = g_esq[k];
            #pragma unroll
            for (int j = 0; j < 8; ++j) {
                float dist = __fadd_rn(__fsub_rn(zsqs[j], __fmul_rn(2.0f, dot[j])), es);
                unsigned long long p =
                    ((unsigned long long)__float_as_uint(dist) << 32) | (unsigned)k;
                if (p < best[j]) best[j] = p;
            }
        }

        for (int j = 0; j < nr; ++j) {
            red[t] = best[j];
            __syncthreads();
            for (int s2 = 256; s2 > 0; s2 >>= 1) {
                if (t < s2) { if (red[t + s2] < red[t]) red[t] = red[t + s2]; }
                __syncthreads();
            }
            if (t == 0) g_idx[rown[j]] = (int)(red[0] & 0xffffffffu);
            __syncthreads();
        }
        __syncthreads();
    }
}

// ============================ kernel 3: output epilogue ====================
__global__ void __launch_bounds__(EP_THREADS)
vq_epilogue_kernel(const float* __restrict__ z, const float* __restrict__ cb,
                   float* __restrict__ out, int out_size) {
    __shared__ int idx_s[EP_ROWS];
    __shared__ double red[EP_THREADS];

    const int t  = threadIdx.x;
    const int n0 = blockIdx.x * EP_ROWS;

    if (t < EP_ROWS) {
        int ii = g_idx[n0 + t];
        idx_s[t] = ii;
        int oi = IDX_OFF + n0 + t;
        if (oi < out_size) out[oi] = (float)ii;
    }
    __syncthreads();

    const int b   = n0 >> 10;
    const int hw0 = n0 & 1023;
    const float* zb = z + ((size_t)b * 256) * 1024 + hw0;
    float*       ob = out + ((size_t)b * 256) * 1024 + hw0;

    const int r  = t & 63;
    const int dq = t >> 6;
    const float* cbrow = cb + (size_t)idx_s[r] * DIMS;

    double accd = 0.0;
    #pragma unroll 4
    for (int p4 = 0; p4 < 16; ++p4) {
        const float4 q4 = *reinterpret_cast<const float4*>(cbrow + dq * 64 + p4 * 4);
        const float qv[4] = {q4.x, q4.y, q4.z, q4.w};
        #pragma unroll
        for (int j = 0; j < 4; ++j) {
            int d = dq * 64 + p4 * 4 + j;
            float zv = zb[(size_t)d * 1024 + r];
            float diff = __fsub_rn(qv[j], zv);
            ob[(size_t)d * 1024 + r] = __fadd_rn(zv, diff);   // straight-through
            accd = fma((double)diff, (double)diff, accd);
        }
    }

    red[t] = accd;
    __syncthreads();
    for (int s = EP_THREADS / 2; s > 0; s >>= 1) {
        if (t < s) red[t] += red[t + s];
        __syncthreads();
    }
    if (t == 0) g_partials[blockIdx.x] = red[0];
}

// ============================ kernel 4: finalize loss ======================
__global__ void vq_finalize_kernel(float* __restrict__ out, int out_size) {
    __shared__ double red[256];
    const int t = threadIdx.x;
    red[t] = g_partials[t] + g_partials[t + 256];
    __syncthreads();
    for (int s = 128; s > 0; s >>= 1) {
        if (t < s) red[t] += red[t + s];
        __syncthreads();
    }
    if (t == 0 && LOSS_OFF < out_size) {
        double mean = red[0] / (double)ZELEMS;
        float m = (float)mean;
        out[LOSS_OFF] = __fadd_rn(m, __fmul_rn(0.25f, m));
    }
}

// ============================ launch ======================================
extern "C" void kernel_launch(void* const* d_in, const int* in_sizes, int n_in,
                              void* d_out, int out_size) {
    const float* z  = (const float*)d_in[0];
    const float* cb = (const float*)d_in[1];
    if (n_in >= 2 && in_sizes[0] == KCODES * DIMS && in_sizes[1] == ZELEMS) {
        const float* tmp = z; z = cb; cb = tmp;
    }
    float* out = (float*)d_out;

    cudaFuncSetAttribute(vq_mma_kernel,
                         cudaFuncAttributeMaxDynamicSharedMemorySize, SM_TOTAL);

    vq_zprep<<<8192, 256>>>(z);
    vq_cbprep<<<KCODES * DIMS / 256, 256>>>(cb);
    vq_esq_kernel<<<KCODES / 8, 256>>>(cb);
    vq_mma_kernel<<<NMMACTA, 256, SM_TOTAL>>>();
    vq_fallback_kernel<<<128, 512>>>(z, cb);
    vq_epilogue_kernel<<<EP_NCTA, EP_THREADS>>>(z, cb, out, out_size);
    vq_finalize_kernel<<<1, 256>>>(out, out_size);
}